// round 7
// baseline (speedup 1.0000x reference)
#include <cuda_runtime.h>
#include <cstdint>
#include <cstddef>

#define N_NODE 50000
#define N_EDGE 625000
#define FD 128
#define EPS 1e-5f
#define TM 128

// ---------------------------------------------------------------------------
// Device scratch (no allocs allowed)
// ---------------------------------------------------------------------------
__device__ float g_agg[(size_t)N_NODE * FD];
__device__ float g_Wt1[128 * 256];  // Wt1[n][k] = tf32(W1[k][n])
__device__ float g_Wt2[128 * 128];
__device__ float g_Wt3[128 * 128];

__device__ __forceinline__ float to_tf32(float x) {
    uint32_t r;
    asm("cvt.rna.tf32.f32 %0, %1;" : "=r"(r) : "f"(x));
    return __uint_as_float(r);
}
__device__ __forceinline__ uint32_t smem_u32(const void* p) {
    uint32_t a;
    asm("{ .reg .u64 t; cvta.to.shared.u64 t, %1; cvt.u32.u64 %0, t; }"
        : "=r"(a) : "l"(p));
    return a;
}
__device__ __forceinline__ void ldsm4(uint32_t a[4], uint32_t addr) {
    asm volatile("ldmatrix.sync.aligned.m8n8.x4.shared.b16 {%0,%1,%2,%3}, [%4];"
                 : "=r"(a[0]), "=r"(a[1]), "=r"(a[2]), "=r"(a[3]) : "r"(addr));
}

#define MMA_TF32(c, a0, a1, a2, a3, b0, b1)                                       \
    asm volatile("mma.sync.aligned.m16n8k8.row.col.f32.tf32.tf32.f32 "            \
                 "{%0,%1,%2,%3}, {%4,%5,%6,%7}, {%8,%9}, {%0,%1,%2,%3};"          \
                 : "+f"((c)[0]), "+f"((c)[1]), "+f"((c)[2]), "+f"((c)[3])         \
                 : "r"(a0), "r"(a1), "r"(a2), "r"(a3), "r"(b0), "r"(b1))

// ---------------------------------------------------------------------------
// Scatter-add edge features (warp/edge, red.global.add.v4) — round-4 version
// ---------------------------------------------------------------------------
__global__ void scatter_edges_kernel(const int* __restrict__ em,
                                     const float* __restrict__ ef) {
    int e = blockIdx.x * 8 + (threadIdx.x >> 5);
    if (e >= N_EDGE) return;
    int lane = threadIdx.x & 31;
    int r = em[N_EDGE + e];
    float4 v = *(const float4*)(ef + (size_t)e * FD + lane * 4);
    float* dst = g_agg + (size_t)r * FD + lane * 4;
    asm volatile("red.global.add.v4.f32 [%0], {%1,%2,%3,%4};"
                 :: "l"(dst), "f"(v.x), "f"(v.y), "f"(v.z), "f"(v.w) : "memory");
}

// ---------------------------------------------------------------------------
// Weight prep: transpose + tf32 round
// ---------------------------------------------------------------------------
__global__ void prep_weights_kernel(const float* __restrict__ W1,
                                    const float* __restrict__ W2,
                                    const float* __restrict__ W3) {
    int i = blockIdx.x * blockDim.x + threadIdx.x;
    if (i < 256 * 128) {
        int k = i >> 7, n = i & 127;
        g_Wt1[n * 256 + k] = to_tf32(W1[i]);
    } else if (i < 256 * 128 + 128 * 128) {
        int j = i - 256 * 128;
        int k = j >> 7, n = j & 127;
        g_Wt2[n * 128 + k] = to_tf32(W2[j]);
    } else if (i < 256 * 128 + 2 * 128 * 128) {
        int j = i - 256 * 128 - 128 * 128;
        int k = j >> 7, n = j & 127;
        g_Wt3[n * 128 + k] = to_tf32(W3[j]);
    }
}

// ---------------------------------------------------------------------------
// Fused MLP + LN + residual. TM=128, 8 warps, warp tile 16x128 (full B
// reuse), k=16 chunk double-buffered staging, register prefetch, ONE
// barrier per chunk. SMEM 111KB -> 2 CTAs/SM.
//   hs stride 132, stage stride 20 (both ==4 / ==20 mod 32: ldmatrix
//   8-row phases hit distinct banks).
// ---------------------------------------------------------------------------
#define HST 132
#define SST 20
#define OFF_HS   0
#define WBUF     2560                  // 128*20 floats per ws buffer
#define OFF_WS   16896                 // 128*132
#define OFF_XS   (OFF_WS + 2 * WBUF)
#define OFF_BIAS (OFF_XS + 2 * WBUF)
#define SMEM_FL  (OFF_BIAS + 640)
#define SMEM_BYTES (SMEM_FL * 4)

__global__ void __launch_bounds__(256, 2)
mlp_mma_kernel(const float* __restrict__ nf,
               const float* __restrict__ b1, const float* __restrict__ b2,
               const float* __restrict__ b3, const float* __restrict__ gamma_p,
               const float* __restrict__ beta_p, float* __restrict__ out) {
    extern __shared__ float smem[];
    float* hs    = smem + OFF_HS;
    float* sBias = smem + OFF_BIAS;

    const int tid = threadIdx.x;
    const int wid = tid >> 5;
    const int lid = tid & 31;
    const int grp = lid >> 2;
    const int tig = lid & 3;
    const int r0 = wid * 16 + grp;
    const int base = blockIdx.x * TM;

    if (tid < 128) {
        sBias[tid]       = b1[tid];
        sBias[128 + tid] = b2[tid];
        sBias[256 + tid] = b3[tid];
        sBias[384 + tid] = gamma_p[tid];
        sBias[512 + tid] = beta_p[tid];
    }

    // ldmatrix lane patterns
    const int a_row = (lid & 7) + ((lid >> 3) & 1) * 8;
    const int a_col = (lid >> 4) * 4;
    const int b_row = (lid & 7) + (lid >> 4) * 8;
    const int b_col = ((lid >> 3) & 1) * 4;

    const uint32_t sb = smem_u32(smem);
    const uint32_t aXb = sb + (uint32_t)((OFF_XS + (wid * 16 + a_row) * SST + a_col) * 4);
    const uint32_t aHb = sb + (uint32_t)((OFF_HS + (wid * 16 + a_row) * HST + a_col) * 4);
    const uint32_t bWb = sb + (uint32_t)((OFF_WS + b_row * SST + b_col) * 4);

    // staging: thread handles rows s_row and s_row+64, k-quad s_q
    const int s_row = tid >> 2;           // 0..63
    const int s_q = tid & 3;              // 0..3
    float* xsST = smem + OFF_XS + s_row * SST + s_q * 4;
    float* wsST = smem + OFF_WS + s_row * SST + s_q * 4;
    const int node0 = base + s_row;
    const int node1 = base + s_row + 64;

    float acc[16][4];
#pragma unroll
    for (int nt = 0; nt < 16; ++nt)
#pragma unroll
        for (int j = 0; j < 4; ++j) acc[nt][j] = 0.f;

    float4 x0, x1, w0, w1;

#define LOADX(kt) do {                                                            \
        int gk = (kt) * 16 + s_q * 4;                                             \
        x0 = make_float4(0.f, 0.f, 0.f, 0.f);                                     \
        x1 = make_float4(0.f, 0.f, 0.f, 0.f);                                     \
        if (node0 < N_NODE)                                                       \
            x0 = (gk < FD) ? *(const float4*)(nf + (size_t)node0 * FD + gk)       \
                           : *(const float4*)(g_agg + (size_t)node0 * FD + gk - FD); \
        if (node1 < N_NODE)                                                       \
            x1 = (gk < FD) ? *(const float4*)(nf + (size_t)node1 * FD + gk)       \
                           : *(const float4*)(g_agg + (size_t)node1 * FD + gk - FD); \
    } while (0)
#define LOADW(Wt, ldw, kt) do {                                                   \
        int gk = (kt) * 16 + s_q * 4;                                             \
        w0 = *(const float4*)((Wt) + (size_t)s_row * (ldw) + gk);                 \
        w1 = *(const float4*)((Wt) + (size_t)(s_row + 64) * (ldw) + gk);          \
    } while (0)
#define STSX(bf) do {                                                             \
        float4 t;                                                                 \
        t.x = to_tf32(x0.x); t.y = to_tf32(x0.y);                                 \
        t.z = to_tf32(x0.z); t.w = to_tf32(x0.w);                                 \
        *(float4*)(xsST + (bf) * WBUF) = t;                                       \
        t.x = to_tf32(x1.x); t.y = to_tf32(x1.y);                                 \
        t.z = to_tf32(x1.z); t.w = to_tf32(x1.w);                                 \
        *(float4*)(xsST + (bf) * WBUF + 64 * SST) = t;                            \
    } while (0)
#define STSW(bf) do {                                                             \
        *(float4*)(wsST + (bf) * WBUF) = w0;                                      \
        *(float4*)(wsST + (bf) * WBUF + 64 * SST) = w1;                           \
    } while (0)
    // one k=16 chunk: 2 A-ldsm + 16 B-ldsm + 32 MMA
#define MMA_CHUNK(abase, bofs)                                                    \
    _Pragma("unroll")                                                             \
    for (int ks = 0; ks < 2; ++ks) {                                              \
        uint32_t a[4];                                                            \
        ldsm4(a, (abase) + (uint32_t)(ks * 32));                                  \
        _Pragma("unroll")                                                         \
        for (int nt2 = 0; nt2 < 8; ++nt2) {                                       \
            uint32_t bfr[4];                                                      \
            ldsm4(bfr, bWb + (bofs) + (uint32_t)(nt2 * 16 * SST * 4 + ks * 32));  \
            MMA_TF32(acc[nt2 * 2],     a[0], a[1], a[2], a[3], bfr[0], bfr[1]);   \
            MMA_TF32(acc[nt2 * 2 + 1], a[0], a[1], a[2], a[3], bfr[2], bfr[3]);   \
        }                                                                         \
    }

    // ------------------ Layer 1: X[128x256] @ Wt1, 16 chunks ------------------
    LOADX(0); LOADW(g_Wt1, 256, 0);
    STSX(0); STSW(0);
    __syncthreads();
    for (int kt = 0; kt < 16; ++kt) {
        int bf = kt & 1;
        if (kt < 15) { LOADX(kt + 1); LOADW(g_Wt1, 256, kt + 1); }
        MMA_CHUNK(aXb + (uint32_t)(bf * WBUF * 4), (uint32_t)(bf * WBUF * 4));
        if (kt < 15) { STSX(1 - bf); STSW(1 - bf); }
        __syncthreads();
    }

    // epilogue 1: bias+relu -> tf32 -> hs (own rows; no cross-warp hazard)
#pragma unroll
    for (int nt = 0; nt < 16; ++nt) {
        int col = nt * 8 + tig * 2;
        float2 v0, v1;
        v0.x = to_tf32(fmaxf(acc[nt][0] + sBias[col], 0.f));
        v0.y = to_tf32(fmaxf(acc[nt][1] + sBias[col + 1], 0.f));
        v1.x = to_tf32(fmaxf(acc[nt][2] + sBias[col], 0.f));
        v1.y = to_tf32(fmaxf(acc[nt][3] + sBias[col + 1], 0.f));
        *(float2*)(hs + r0 * HST + col) = v0;
        *(float2*)(hs + (r0 + 8) * HST + col) = v1;
    }

    // ------------------ Layers 2 & 3: H[128x128] @ Wt, 8 chunks ------------------
    for (int l = 0; l < 2; ++l) {
        const float* Wt = l ? g_Wt3 : g_Wt2;
#pragma unroll
        for (int nt = 0; nt < 16; ++nt)
#pragma unroll
            for (int j = 0; j < 4; ++j) acc[nt][j] = 0.f;

        LOADW(Wt, 128, 0);
        STSW(0);
        __syncthreads();
        for (int kt = 0; kt < 8; ++kt) {
            int bf = kt & 1;
            if (kt < 7) LOADW(Wt, 128, kt + 1);
            MMA_CHUNK(aHb + (uint32_t)(kt * 64), (uint32_t)(bf * WBUF * 4));
            if (kt < 7) STSW(1 - bf);
            __syncthreads();
        }

        if (l == 0) {
#pragma unroll
            for (int nt = 0; nt < 16; ++nt) {
                int col = nt * 8 + tig * 2;
                float2 v0, v1;
                v0.x = to_tf32(fmaxf(acc[nt][0] + sBias[128 + col], 0.f));
                v0.y = to_tf32(fmaxf(acc[nt][1] + sBias[128 + col + 1], 0.f));
                v1.x = to_tf32(fmaxf(acc[nt][2] + sBias[128 + col], 0.f));
                v1.y = to_tf32(fmaxf(acc[nt][3] + sBias[128 + col + 1], 0.f));
                *(float2*)(hs + r0 * HST + col) = v0;
                *(float2*)(hs + (r0 + 8) * HST + col) = v1;
            }
        }
    }

    // ------------- Final: +b3, LayerNorm, gamma/beta, residual -------------
    {
        float s0 = 0.f, sq0 = 0.f, s1 = 0.f, sq1 = 0.f;
#pragma unroll
        for (int nt = 0; nt < 16; ++nt) {
            int col = nt * 8 + tig * 2;
            acc[nt][0] += sBias[256 + col];
            acc[nt][1] += sBias[256 + col + 1];
            acc[nt][2] += sBias[256 + col];
            acc[nt][3] += sBias[256 + col + 1];
            s0 += acc[nt][0] + acc[nt][1];
            sq0 += acc[nt][0] * acc[nt][0] + acc[nt][1] * acc[nt][1];
            s1 += acc[nt][2] + acc[nt][3];
            sq1 += acc[nt][2] * acc[nt][2] + acc[nt][3] * acc[nt][3];
        }
#pragma unroll
        for (int o = 1; o <= 2; o <<= 1) {
            s0 += __shfl_xor_sync(0xFFFFFFFFu, s0, o);
            sq0 += __shfl_xor_sync(0xFFFFFFFFu, sq0, o);
            s1 += __shfl_xor_sync(0xFFFFFFFFu, s1, o);
            sq1 += __shfl_xor_sync(0xFFFFFFFFu, sq1, o);
        }
        float mu0 = s0 * (1.f / 128.f);
        float ri0 = rsqrtf(sq0 * (1.f / 128.f) - mu0 * mu0 + EPS);
        float mu1 = s1 * (1.f / 128.f);
        float ri1 = rsqrtf(sq1 * (1.f / 128.f) - mu1 * mu1 + EPS);

        int n0 = base + r0;
        int n1 = base + r0 + 8;
#pragma unroll
        for (int nt = 0; nt < 16; ++nt) {
            int col = nt * 8 + tig * 2;
            float g0 = sBias[384 + col], g1 = sBias[384 + col + 1];
            float be0 = sBias[512 + col], be1 = sBias[512 + col + 1];
            if (n0 < N_NODE) {
                float2 nv = *(const float2*)(nf + (size_t)n0 * FD + col);
                float2 o;
                o.x = (acc[nt][0] - mu0) * ri0 * g0 + be0 + nv.x;
                o.y = (acc[nt][1] - mu0) * ri0 * g1 + be1 + nv.y;
                *(float2*)(out + (size_t)n0 * FD + col) = o;
            }
            if (n1 < N_NODE) {
                float2 nv = *(const float2*)(nf + (size_t)n1 * FD + col);
                float2 o;
                o.x = (acc[nt][2] - mu1) * ri1 * g0 + be0 + nv.x;
                o.y = (acc[nt][3] - mu1) * ri1 * g1 + be1 + nv.y;
                *(float2*)(out + (size_t)n1 * FD + col) = o;
            }
        }
    }
}

// ---------------------------------------------------------------------------
extern "C" void kernel_launch(void* const* d_in, const int* in_sizes, int n_in,
                              void* d_out, int out_size) {
    const float* node_feature = (const float*)d_in[0];
    const int* edge_matrix    = (const int*)d_in[1];
    const float* edge_feature = (const float*)d_in[2];
    const float* W1 = (const float*)d_in[3];
    const float* b1 = (const float*)d_in[4];
    const float* W2 = (const float*)d_in[5];
    const float* b2 = (const float*)d_in[6];
    const float* W3 = (const float*)d_in[7];
    const float* b3 = (const float*)d_in[8];
    const float* gamma = (const float*)d_in[9];
    const float* beta  = (const float*)d_in[10];
    float* out = (float*)d_out;

    static void* agg_ptr = nullptr;
    static int inited = 0;
    if (!inited) {
        cudaGetSymbolAddress(&agg_ptr, g_agg);
        cudaFuncSetAttribute(mlp_mma_kernel,
                             cudaFuncAttributeMaxDynamicSharedMemorySize, SMEM_BYTES);
        inited = 1;
    }

    cudaMemsetAsync(agg_ptr, 0, (size_t)N_NODE * FD * sizeof(float));

    scatter_edges_kernel<<<(N_EDGE + 7) / 8, 256>>>(edge_matrix, edge_feature);

    prep_weights_kernel<<<(256 * 128 + 2 * 128 * 128 + 255) / 256, 256>>>(W1, W2, W3);

    int grid = (N_NODE + TM - 1) / TM;
    mlp_mma_kernel<<<grid, 256, SMEM_BYTES>>>(node_feature, b1, b2, b3,
                                              gamma, beta, out);
}

// round 8
// speedup vs baseline: 1.1034x; 1.1034x over previous
#include <cuda_runtime.h>
#include <cstdint>
#include <cstddef>

#define N_NODE 50000
#define N_EDGE 625000
#define FD 128
#define EPS 1e-5f
#define TM 128

// ---------------------------------------------------------------------------
// Device scratch (no allocs allowed)
// ---------------------------------------------------------------------------
__device__ float g_agg[(size_t)N_NODE * FD];
__device__ float g_h1a[(size_t)N_NODE * FD];   // partial layer-1 acc (nf half)
__device__ float g_Wt1[128 * 256];  // Wt1[n][k] = tf32(W1[k][n])
__device__ float g_Wt2[128 * 128];
__device__ float g_Wt3[128 * 128];

__device__ __forceinline__ float to_tf32(float x) {
    uint32_t r;
    asm("cvt.rna.tf32.f32 %0, %1;" : "=r"(r) : "f"(x));
    return __uint_as_float(r);
}
__device__ __forceinline__ uint32_t smem_u32(const void* p) {
    uint32_t a;
    asm("{ .reg .u64 t; cvta.to.shared.u64 t, %1; cvt.u32.u64 %0, t; }"
        : "=r"(a) : "l"(p));
    return a;
}
__device__ __forceinline__ void ldsm4(uint32_t a[4], uint32_t addr) {
    asm volatile("ldmatrix.sync.aligned.m8n8.x4.shared.b16 {%0,%1,%2,%3}, [%4];"
                 : "=r"(a[0]), "=r"(a[1]), "=r"(a[2]), "=r"(a[3]) : "r"(addr));
}

#define MMA_TF32(c, a0, a1, a2, a3, b0, b1)                                       \
    asm volatile("mma.sync.aligned.m16n8k8.row.col.f32.tf32.tf32.f32 "            \
                 "{%0,%1,%2,%3}, {%4,%5,%6,%7}, {%8,%9}, {%0,%1,%2,%3};"          \
                 : "+f"((c)[0]), "+f"((c)[1]), "+f"((c)[2]), "+f"((c)[3])         \
                 : "r"(a0), "r"(a1), "r"(a2), "r"(a3), "r"(b0), "r"(b1))

// ---------------------------------------------------------------------------
// Scatter-add edge features (warp/edge, red.global.add.v4)
// ---------------------------------------------------------------------------
__global__ void scatter_edges_kernel(const int* __restrict__ em,
                                     const float* __restrict__ ef) {
    int e = blockIdx.x * 8 + (threadIdx.x >> 5);
    if (e >= N_EDGE) return;
    int lane = threadIdx.x & 31;
    int r = em[N_EDGE + e];
    float4 v = *(const float4*)(ef + (size_t)e * FD + lane * 4);
    float* dst = g_agg + (size_t)r * FD + lane * 4;
    asm volatile("red.global.add.v4.f32 [%0], {%1,%2,%3,%4};"
                 :: "l"(dst), "f"(v.x), "f"(v.y), "f"(v.z), "f"(v.w) : "memory");
}

// ---------------------------------------------------------------------------
// Weight prep: transpose + tf32 round
// ---------------------------------------------------------------------------
__global__ void prep_weights_kernel(const float* __restrict__ W1,
                                    const float* __restrict__ W2,
                                    const float* __restrict__ W3) {
    int i = blockIdx.x * blockDim.x + threadIdx.x;
    if (i < 256 * 128) {
        int k = i >> 7, n = i & 127;
        g_Wt1[n * 256 + k] = to_tf32(W1[i]);
    } else if (i < 256 * 128 + 128 * 128) {
        int j = i - 256 * 128;
        int k = j >> 7, n = j & 127;
        g_Wt2[n * 128 + k] = to_tf32(W2[j]);
    } else if (i < 256 * 128 + 2 * 128 * 128) {
        int j = i - 256 * 128 - 128 * 128;
        int k = j >> 7, n = j & 127;
        g_Wt3[n * 128 + k] = to_tf32(W3[j]);
    }
}

// ---------------------------------------------------------------------------
// Phase 1: P = tf32(nf) @ Wt1[:, 0:128]  (independent of scatter; runs on
// the forked stream, hidden under the scatter). Round-4 tile structure.
// ---------------------------------------------------------------------------
#define ST36 36
#define P1_FLOATS (2 * 128 * ST36)
#define P1_BYTES (P1_FLOATS * 4)

__global__ void __launch_bounds__(256, 2)
gemm_nf_kernel(const float* __restrict__ nf) {
    extern __shared__ float smem[];
    float* xs = smem;
    float* ws = smem + 128 * ST36;

    const int tid = threadIdx.x;
    const int wid = tid >> 5;
    const int lid = tid & 31;
    const int grp = lid >> 2;
    const int tig = lid & 3;
    const int r0 = wid * 16 + grp;
    const int base = blockIdx.x * TM;

    const int a_row = (lid & 7) + ((lid >> 3) & 1) * 8;
    const int a_col = (lid >> 4) * 4;
    const int b_row = (lid & 7) + (lid >> 4) * 8;
    const int b_col = ((lid >> 3) & 1) * 4;

    const uint32_t aX = smem_u32(xs) + (uint32_t)(((wid * 16 + a_row) * ST36 + a_col) * 4);
    const uint32_t bW = smem_u32(ws) + (uint32_t)((b_row * ST36 + b_col) * 4);

    float acc[16][4];
#pragma unroll
    for (int nt = 0; nt < 16; ++nt)
#pragma unroll
        for (int j = 0; j < 4; ++j) acc[nt][j] = 0.f;

    for (int kt = 0; kt < 4; ++kt) {
#pragma unroll
        for (int it = 0; it < 4; ++it) {
            int i = tid + it * 256;
            int row = i >> 3, q = i & 7;
            int gk = kt * 32 + q * 4;
            float4 v = make_float4(0.f, 0.f, 0.f, 0.f);
            int node = base + row;
            if (node < N_NODE) v = *(const float4*)(nf + (size_t)node * FD + gk);
            v.x = to_tf32(v.x); v.y = to_tf32(v.y);
            v.z = to_tf32(v.z); v.w = to_tf32(v.w);
            *(float4*)(xs + row * ST36 + q * 4) = v;
            float4 w = *(const float4*)(g_Wt1 + (size_t)row * 256 + gk);
            *(float4*)(ws + row * ST36 + q * 4) = w;
        }
        __syncthreads();
#pragma unroll
        for (int ks = 0; ks < 4; ++ks) {
            uint32_t a[4];
            ldsm4(a, aX + (uint32_t)(ks * 8 * 4));
#pragma unroll
            for (int nt2 = 0; nt2 < 8; ++nt2) {
                uint32_t b[4];
                ldsm4(b, bW + (uint32_t)((nt2 * 16 * ST36 + ks * 8) * 4));
                MMA_TF32(acc[nt2 * 2],     a[0], a[1], a[2], a[3], b[0], b[1]);
                MMA_TF32(acc[nt2 * 2 + 1], a[0], a[1], a[2], a[3], b[2], b[3]);
            }
        }
        __syncthreads();
    }

    int n0 = base + r0;
    int n1 = base + r0 + 8;
#pragma unroll
    for (int nt = 0; nt < 16; ++nt) {
        int col = nt * 8 + tig * 2;
        if (n0 < N_NODE)
            *(float2*)(g_h1a + (size_t)n0 * FD + col) = make_float2(acc[nt][0], acc[nt][1]);
        if (n1 < N_NODE)
            *(float2*)(g_h1a + (size_t)n1 * FD + col) = make_float2(acc[nt][2], acc[nt][3]);
    }
}

// ---------------------------------------------------------------------------
// Phase 2: fused MLP (layer1 agg-half with acc init from g_h1a; layers 2,3)
// + LayerNorm + residual. EXACT round-4 tile structure (best measured).
// ---------------------------------------------------------------------------
#define XS_STRIDE 36
#define WS_STRIDE 36
#define HS_STRIDE 132
#define SMEM_FLOATS (128 * HS_STRIDE + 128 * WS_STRIDE + 128 * XS_STRIDE + 5 * 128)
#define SMEM_BYTES (SMEM_FLOATS * 4)

__global__ void __launch_bounds__(256, 2)
mlp_mma_kernel(const float* __restrict__ nf,
               const float* __restrict__ b1, const float* __restrict__ b2,
               const float* __restrict__ b3, const float* __restrict__ gamma_p,
               const float* __restrict__ beta_p, float* __restrict__ out) {
    extern __shared__ float smem[];
    float* hs = smem;
    float* ws = hs + 128 * HS_STRIDE;
    float* xs = ws + 128 * WS_STRIDE;
    float* sBias = xs + 128 * XS_STRIDE;

    const int tid = threadIdx.x;
    const int wid = tid >> 5;
    const int lid = tid & 31;
    const int grp = lid >> 2;
    const int tig = lid & 3;
    const int r0 = wid * 16 + grp;
    const int base = blockIdx.x * TM;

    if (tid < 128) {
        sBias[tid]       = b1[tid];
        sBias[128 + tid] = b2[tid];
        sBias[256 + tid] = b3[tid];
        sBias[384 + tid] = gamma_p[tid];
        sBias[512 + tid] = beta_p[tid];
    }

    const int a_row = (lid & 7) + ((lid >> 3) & 1) * 8;
    const int a_col = (lid >> 4) * 4;
    const int b_row = (lid & 7) + (lid >> 4) * 8;
    const int b_col = ((lid >> 3) & 1) * 4;

    const uint32_t aX = smem_u32(xs) + (uint32_t)(((wid * 16 + a_row) * XS_STRIDE + a_col) * 4);
    const uint32_t aH = smem_u32(hs) + (uint32_t)(((wid * 16 + a_row) * HS_STRIDE + a_col) * 4);
    const uint32_t bW = smem_u32(ws) + (uint32_t)((b_row * WS_STRIDE + b_col) * 4);

    const int n0 = base + r0;
    const int n1 = base + r0 + 8;

    // acc init = phase-1 partial (nf @ W1[0:128])
    float acc[16][4];
#pragma unroll
    for (int nt = 0; nt < 16; ++nt) {
        int col = nt * 8 + tig * 2;
        float2 p0 = make_float2(0.f, 0.f), p1 = make_float2(0.f, 0.f);
        if (n0 < N_NODE) p0 = *(const float2*)(g_h1a + (size_t)n0 * FD + col);
        if (n1 < N_NODE) p1 = *(const float2*)(g_h1a + (size_t)n1 * FD + col);
        acc[nt][0] = p0.x; acc[nt][1] = p0.y;
        acc[nt][2] = p1.x; acc[nt][3] = p1.y;
    }

    // Layer 1 (agg half): agg[128] @ W1[128:256], 4 k-chunks
    for (int kt = 0; kt < 4; ++kt) {
#pragma unroll
        for (int it = 0; it < 4; ++it) {
            int i = tid + it * 256;
            int row = i >> 3, q = i & 7;
            int gk = kt * 32 + q * 4;
            float4 v = make_float4(0.f, 0.f, 0.f, 0.f);
            int node = base + row;
            if (node < N_NODE)
                v = *(const float4*)(g_agg + (size_t)node * FD + gk);
            v.x = to_tf32(v.x); v.y = to_tf32(v.y);
            v.z = to_tf32(v.z); v.w = to_tf32(v.w);
            *(float4*)(xs + row * XS_STRIDE + q * 4) = v;
            float4 w = *(const float4*)(g_Wt1 + (size_t)row * 256 + 128 + gk);
            *(float4*)(ws + row * WS_STRIDE + q * 4) = w;
        }
        __syncthreads();
#pragma unroll
        for (int ks = 0; ks < 4; ++ks) {
            uint32_t a[4];
            ldsm4(a, aX + (uint32_t)(ks * 8 * 4));
#pragma unroll
            for (int nt2 = 0; nt2 < 8; ++nt2) {
                uint32_t b[4];
                ldsm4(b, bW + (uint32_t)((nt2 * 16 * WS_STRIDE + ks * 8) * 4));
                MMA_TF32(acc[nt2 * 2],     a[0], a[1], a[2], a[3], b[0], b[1]);
                MMA_TF32(acc[nt2 * 2 + 1], a[0], a[1], a[2], a[3], b[2], b[3]);
            }
        }
        __syncthreads();
    }

    // epilogue 1: bias+relu -> tf32 -> hs
#pragma unroll
    for (int nt = 0; nt < 16; ++nt) {
        int col = nt * 8 + tig * 2;
        float2 v0, v1;
        v0.x = to_tf32(fmaxf(acc[nt][0] + sBias[col], 0.f));
        v0.y = to_tf32(fmaxf(acc[nt][1] + sBias[col + 1], 0.f));
        v1.x = to_tf32(fmaxf(acc[nt][2] + sBias[col], 0.f));
        v1.y = to_tf32(fmaxf(acc[nt][3] + sBias[col + 1], 0.f));
        *(float2*)(hs + r0 * HS_STRIDE + col) = v0;
        *(float2*)(hs + (r0 + 8) * HS_STRIDE + col) = v1;
    }
    __syncthreads();

    // Layers 2 and 3
    for (int l = 0; l < 2; ++l) {
        const float* Wt = l ? g_Wt3 : g_Wt2;
#pragma unroll
        for (int nt = 0; nt < 16; ++nt)
#pragma unroll
            for (int j = 0; j < 4; ++j) acc[nt][j] = 0.f;

        for (int kt = 0; kt < 4; ++kt) {
#pragma unroll
            for (int it = 0; it < 4; ++it) {
                int i = tid + it * 256;
                int n = i >> 3, q = i & 7;
                float4 w = *(const float4*)(Wt + (size_t)n * 128 + kt * 32 + q * 4);
                *(float4*)(ws + n * WS_STRIDE + q * 4) = w;
            }
            __syncthreads();
#pragma unroll
            for (int ks = 0; ks < 4; ++ks) {
                uint32_t a[4];
                ldsm4(a, aH + (uint32_t)((kt * 32 + ks * 8) * 4));
#pragma unroll
                for (int nt2 = 0; nt2 < 8; ++nt2) {
                    uint32_t b[4];
                    ldsm4(b, bW + (uint32_t)((nt2 * 16 * WS_STRIDE + ks * 8) * 4));
                    MMA_TF32(acc[nt2 * 2],     a[0], a[1], a[2], a[3], b[0], b[1]);
                    MMA_TF32(acc[nt2 * 2 + 1], a[0], a[1], a[2], a[3], b[2], b[3]);
                }
            }
            __syncthreads();
        }

        if (l == 0) {
#pragma unroll
            for (int nt = 0; nt < 16; ++nt) {
                int col = nt * 8 + tig * 2;
                float2 v0, v1;
                v0.x = to_tf32(fmaxf(acc[nt][0] + sBias[128 + col], 0.f));
                v0.y = to_tf32(fmaxf(acc[nt][1] + sBias[128 + col + 1], 0.f));
                v1.x = to_tf32(fmaxf(acc[nt][2] + sBias[128 + col], 0.f));
                v1.y = to_tf32(fmaxf(acc[nt][3] + sBias[128 + col + 1], 0.f));
                *(float2*)(hs + r0 * HS_STRIDE + col) = v0;
                *(float2*)(hs + (r0 + 8) * HS_STRIDE + col) = v1;
            }
            __syncthreads();
        }
    }

    // Final: +b3, LayerNorm, gamma/beta, residual
    {
        float s0 = 0.f, sq0 = 0.f, s1 = 0.f, sq1 = 0.f;
#pragma unroll
        for (int nt = 0; nt < 16; ++nt) {
            int col = nt * 8 + tig * 2;
            acc[nt][0] += sBias[256 + col];
            acc[nt][1] += sBias[256 + col + 1];
            acc[nt][2] += sBias[256 + col];
            acc[nt][3] += sBias[256 + col + 1];
            s0 += acc[nt][0] + acc[nt][1];
            sq0 += acc[nt][0] * acc[nt][0] + acc[nt][1] * acc[nt][1];
            s1 += acc[nt][2] + acc[nt][3];
            sq1 += acc[nt][2] * acc[nt][2] + acc[nt][3] * acc[nt][3];
        }
#pragma unroll
        for (int o = 1; o <= 2; o <<= 1) {
            s0 += __shfl_xor_sync(0xFFFFFFFFu, s0, o);
            sq0 += __shfl_xor_sync(0xFFFFFFFFu, sq0, o);
            s1 += __shfl_xor_sync(0xFFFFFFFFu, s1, o);
            sq1 += __shfl_xor_sync(0xFFFFFFFFu, sq1, o);
        }
        float mu0 = s0 * (1.f / 128.f);
        float ri0 = rsqrtf(sq0 * (1.f / 128.f) - mu0 * mu0 + EPS);
        float mu1 = s1 * (1.f / 128.f);
        float ri1 = rsqrtf(sq1 * (1.f / 128.f) - mu1 * mu1 + EPS);

#pragma unroll
        for (int nt = 0; nt < 16; ++nt) {
            int col = nt * 8 + tig * 2;
            float g0 = sBias[384 + col], g1 = sBias[384 + col + 1];
            float be0 = sBias[512 + col], be1 = sBias[512 + col + 1];
            if (n0 < N_NODE) {
                float2 nv = *(const float2*)(nf + (size_t)n0 * FD + col);
                float2 o;
                o.x = (acc[nt][0] - mu0) * ri0 * g0 + be0 + nv.x;
                o.y = (acc[nt][1] - mu0) * ri0 * g1 + be1 + nv.y;
                *(float2*)(out + (size_t)n0 * FD + col) = o;
            }
            if (n1 < N_NODE) {
                float2 nv = *(const float2*)(nf + (size_t)n1 * FD + col);
                float2 o;
                o.x = (acc[nt][2] - mu1) * ri1 * g0 + be0 + nv.x;
                o.y = (acc[nt][3] - mu1) * ri1 * g1 + be1 + nv.y;
                *(float2*)(out + (size_t)n1 * FD + col) = o;
            }
        }
    }
}

// ---------------------------------------------------------------------------
extern "C" void kernel_launch(void* const* d_in, const int* in_sizes, int n_in,
                              void* d_out, int out_size) {
    const float* node_feature = (const float*)d_in[0];
    const int* edge_matrix    = (const int*)d_in[1];
    const float* edge_feature = (const float*)d_in[2];
    const float* W1 = (const float*)d_in[3];
    const float* b1 = (const float*)d_in[4];
    const float* W2 = (const float*)d_in[5];
    const float* b2 = (const float*)d_in[6];
    const float* W3 = (const float*)d_in[7];
    const float* b3 = (const float*)d_in[8];
    const float* gamma = (const float*)d_in[9];
    const float* beta  = (const float*)d_in[10];
    float* out = (float*)d_out;

    static void* agg_ptr = nullptr;
    static cudaStream_t s2;
    static cudaEvent_t evFork, evJoin;
    static int inited = 0;
    if (!inited) {
        cudaGetSymbolAddress(&agg_ptr, g_agg);
        cudaFuncSetAttribute(mlp_mma_kernel,
                             cudaFuncAttributeMaxDynamicSharedMemorySize, SMEM_BYTES);
        cudaFuncSetAttribute(gemm_nf_kernel,
                             cudaFuncAttributeMaxDynamicSharedMemorySize, P1_BYTES);
        cudaStreamCreateWithFlags(&s2, cudaStreamNonBlocking);
        cudaEventCreateWithFlags(&evFork, cudaEventDisableTiming);
        cudaEventCreateWithFlags(&evJoin, cudaEventDisableTiming);
        inited = 1;
    }

    int grid = (N_NODE + TM - 1) / TM;

    // fork: prep + phase-1 GEMM on s2 (independent of scatter)
    cudaEventRecord(evFork, 0);
    cudaStreamWaitEvent(s2, evFork, 0);
    prep_weights_kernel<<<(256 * 128 + 2 * 128 * 128 + 255) / 256, 256, 0, s2>>>(W1, W2, W3);
    gemm_nf_kernel<<<grid, 256, P1_BYTES, s2>>>(node_feature);
    cudaEventRecord(evJoin, s2);

    // main: memset + scatter
    cudaMemsetAsync(agg_ptr, 0, (size_t)N_NODE * FD * sizeof(float));
    scatter_edges_kernel<<<(N_EDGE + 7) / 8, 256>>>(edge_matrix, edge_feature);

    // join, then phase-2 fused MLP
    cudaStreamWaitEvent(0, evJoin, 0);
    mlp_mma_kernel<<<grid, 256, SMEM_BYTES>>>(node_feature, b1, b2, b3,
                                              gamma, beta, out);
}

// round 9
// speedup vs baseline: 1.2211x; 1.1067x over previous
#include <cuda_runtime.h>
#include <cstdint>
#include <cstddef>

#define N_NODE 50000
#define N_EDGE 625000
#define FD 128
#define EPS 1e-5f
#define TM 128

// ---------------------------------------------------------------------------
// Device scratch (no allocs allowed)
// ---------------------------------------------------------------------------
__device__ float g_agg[(size_t)N_NODE * FD];
__device__ float g_Wt1[128 * 256];  // Wt1[n][k] = tf32(W1[k][n])
__device__ float g_Wt2[128 * 128];
__device__ float g_Wt3[128 * 128];

__device__ __forceinline__ float to_tf32(float x) {
    uint32_t r;
    asm("cvt.rna.tf32.f32 %0, %1;" : "=r"(r) : "f"(x));
    return __uint_as_float(r);
}
__device__ __forceinline__ uint32_t smem_u32(const void* p) {
    uint32_t a;
    asm("{ .reg .u64 t; cvta.to.shared.u64 t, %1; cvt.u32.u64 %0, t; }"
        : "=r"(a) : "l"(p));
    return a;
}
__device__ __forceinline__ void ldsm4(uint32_t a[4], uint32_t addr) {
    asm volatile("ldmatrix.sync.aligned.m8n8.x4.shared.b16 {%0,%1,%2,%3}, [%4];"
                 : "=r"(a[0]), "=r"(a[1]), "=r"(a[2]), "=r"(a[3]) : "r"(addr));
}

#define MMA_TF32(c, a0, a1, a2, a3, b0, b1)                                       \
    asm volatile("mma.sync.aligned.m16n8k8.row.col.f32.tf32.tf32.f32 "            \
                 "{%0,%1,%2,%3}, {%4,%5,%6,%7}, {%8,%9}, {%0,%1,%2,%3};"          \
                 : "+f"((c)[0]), "+f"((c)[1]), "+f"((c)[2]), "+f"((c)[3])         \
                 : "r"(a0), "r"(a1), "r"(a2), "r"(a3), "r"(b0), "r"(b1))

// ---------------------------------------------------------------------------
// Scatter-add: 4 edges per warp, all LDGs issued before the REDs (MLP=4).
// ---------------------------------------------------------------------------
__global__ void scatter_edges_kernel(const int* __restrict__ em,
                                     const float* __restrict__ ef) {
    int e0 = (blockIdx.x * 8 + (threadIdx.x >> 5)) * 4;
    int lane = threadIdx.x & 31;
    if (e0 + 3 < N_EDGE) {
        // fast path: batch the 4 index loads, 4 vector loads, then 4 REDs
        int r0 = em[N_EDGE + e0];
        int r1 = em[N_EDGE + e0 + 1];
        int r2 = em[N_EDGE + e0 + 2];
        int r3 = em[N_EDGE + e0 + 3];
        float4 v0 = *(const float4*)(ef + (size_t)(e0    ) * FD + lane * 4);
        float4 v1 = *(const float4*)(ef + (size_t)(e0 + 1) * FD + lane * 4);
        float4 v2 = *(const float4*)(ef + (size_t)(e0 + 2) * FD + lane * 4);
        float4 v3 = *(const float4*)(ef + (size_t)(e0 + 3) * FD + lane * 4);
        asm volatile("red.global.add.v4.f32 [%0], {%1,%2,%3,%4};"
                     :: "l"(g_agg + (size_t)r0 * FD + lane * 4),
                        "f"(v0.x), "f"(v0.y), "f"(v0.z), "f"(v0.w) : "memory");
        asm volatile("red.global.add.v4.f32 [%0], {%1,%2,%3,%4};"
                     :: "l"(g_agg + (size_t)r1 * FD + lane * 4),
                        "f"(v1.x), "f"(v1.y), "f"(v1.z), "f"(v1.w) : "memory");
        asm volatile("red.global.add.v4.f32 [%0], {%1,%2,%3,%4};"
                     :: "l"(g_agg + (size_t)r2 * FD + lane * 4),
                        "f"(v2.x), "f"(v2.y), "f"(v2.z), "f"(v2.w) : "memory");
        asm volatile("red.global.add.v4.f32 [%0], {%1,%2,%3,%4};"
                     :: "l"(g_agg + (size_t)r3 * FD + lane * 4),
                        "f"(v3.x), "f"(v3.y), "f"(v3.z), "f"(v3.w) : "memory");
    } else {
        for (int i = 0; i < 4; ++i) {
            int e = e0 + i;
            if (e >= N_EDGE) break;
            int r = em[N_EDGE + e];
            float4 v = *(const float4*)(ef + (size_t)e * FD + lane * 4);
            asm volatile("red.global.add.v4.f32 [%0], {%1,%2,%3,%4};"
                         :: "l"(g_agg + (size_t)r * FD + lane * 4),
                            "f"(v.x), "f"(v.y), "f"(v.z), "f"(v.w) : "memory");
        }
    }
}

// ---------------------------------------------------------------------------
// Weight prep: transpose + tf32 round
// ---------------------------------------------------------------------------
__global__ void prep_weights_kernel(const float* __restrict__ W1,
                                    const float* __restrict__ W2,
                                    const float* __restrict__ W3) {
    int i = blockIdx.x * blockDim.x + threadIdx.x;
    if (i < 256 * 128) {
        int k = i >> 7, n = i & 127;
        g_Wt1[n * 256 + k] = to_tf32(W1[i]);
    } else if (i < 256 * 128 + 128 * 128) {
        int j = i - 256 * 128;
        int k = j >> 7, n = j & 127;
        g_Wt2[n * 128 + k] = to_tf32(W2[j]);
    } else if (i < 256 * 128 + 2 * 128 * 128) {
        int j = i - 256 * 128 - 128 * 128;
        int k = j >> 7, n = j & 127;
        g_Wt3[n * 128 + k] = to_tf32(W3[j]);
    }
}

// ---------------------------------------------------------------------------
// Fused tf32 mma.sync MLP + LN + residual — round-4 structure (frozen).
// ---------------------------------------------------------------------------
#define XS_STRIDE 36
#define WS_STRIDE 36
#define HS_STRIDE 132
#define SMEM_FLOATS (128 * HS_STRIDE + 128 * WS_STRIDE + 128 * XS_STRIDE + 5 * 128)
#define SMEM_BYTES (SMEM_FLOATS * 4)

__global__ void __launch_bounds__(256, 2)
mlp_mma_kernel(const float* __restrict__ nf,
               const float* __restrict__ b1, const float* __restrict__ b2,
               const float* __restrict__ b3, const float* __restrict__ gamma_p,
               const float* __restrict__ beta_p, float* __restrict__ out) {
    extern __shared__ float smem[];
    float* hs = smem;
    float* ws = hs + 128 * HS_STRIDE;
    float* xs = ws + 128 * WS_STRIDE;
    float* sBias = xs + 128 * XS_STRIDE;

    const int tid = threadIdx.x;
    const int wid = tid >> 5;
    const int lid = tid & 31;
    const int grp = lid >> 2;
    const int tig = lid & 3;
    const int r0 = wid * 16 + grp;
    const int base = blockIdx.x * TM;

    if (tid < 128) {
        sBias[tid]       = b1[tid];
        sBias[128 + tid] = b2[tid];
        sBias[256 + tid] = b3[tid];
        sBias[384 + tid] = gamma_p[tid];
        sBias[512 + tid] = beta_p[tid];
    }

    const int a_row = (lid & 7) + ((lid >> 3) & 1) * 8;
    const int a_col = (lid >> 4) * 4;
    const int b_row = (lid & 7) + (lid >> 4) * 8;
    const int b_col = ((lid >> 3) & 1) * 4;

    const uint32_t aX = smem_u32(xs) + (uint32_t)(((wid * 16 + a_row) * XS_STRIDE + a_col) * 4);
    const uint32_t aH = smem_u32(hs) + (uint32_t)(((wid * 16 + a_row) * HS_STRIDE + a_col) * 4);
    const uint32_t bW = smem_u32(ws) + (uint32_t)((b_row * WS_STRIDE + b_col) * 4);

    float acc[16][4];
#pragma unroll
    for (int nt = 0; nt < 16; ++nt)
#pragma unroll
        for (int j = 0; j < 4; ++j) acc[nt][j] = 0.f;

    // Layer 1: X[128x256] @ W1
    for (int kt = 0; kt < 8; ++kt) {
#pragma unroll
        for (int it = 0; it < 4; ++it) {
            int i = tid + it * 256;
            int row = i >> 3, q = i & 7;
            int gk = kt * 32 + q * 4;
            float4 v = make_float4(0.f, 0.f, 0.f, 0.f);
            int node = base + row;
            if (node < N_NODE) {
                const float* src = (gk < FD)
                    ? nf + (size_t)node * FD + gk
                    : g_agg + (size_t)node * FD + (gk - FD);
                v = *(const float4*)src;
            }
            v.x = to_tf32(v.x); v.y = to_tf32(v.y);
            v.z = to_tf32(v.z); v.w = to_tf32(v.w);
            *(float4*)(xs + row * XS_STRIDE + q * 4) = v;
            float4 w = *(const float4*)(g_Wt1 + (size_t)row * 256 + gk);
            *(float4*)(ws + row * WS_STRIDE + q * 4) = w;
        }
        __syncthreads();
#pragma unroll
        for (int ks = 0; ks < 4; ++ks) {
            uint32_t a[4];
            ldsm4(a, aX + (uint32_t)(ks * 8 * 4));
#pragma unroll
            for (int nt2 = 0; nt2 < 8; ++nt2) {
                uint32_t b[4];
                ldsm4(b, bW + (uint32_t)((nt2 * 16 * WS_STRIDE + ks * 8) * 4));
                MMA_TF32(acc[nt2 * 2],     a[0], a[1], a[2], a[3], b[0], b[1]);
                MMA_TF32(acc[nt2 * 2 + 1], a[0], a[1], a[2], a[3], b[2], b[3]);
            }
        }
        __syncthreads();
    }

    // epilogue 1
#pragma unroll
    for (int nt = 0; nt < 16; ++nt) {
        int col = nt * 8 + tig * 2;
        float2 v0, v1;
        v0.x = to_tf32(fmaxf(acc[nt][0] + sBias[col], 0.f));
        v0.y = to_tf32(fmaxf(acc[nt][1] + sBias[col + 1], 0.f));
        v1.x = to_tf32(fmaxf(acc[nt][2] + sBias[col], 0.f));
        v1.y = to_tf32(fmaxf(acc[nt][3] + sBias[col + 1], 0.f));
        *(float2*)(hs + r0 * HS_STRIDE + col) = v0;
        *(float2*)(hs + (r0 + 8) * HS_STRIDE + col) = v1;
    }
    __syncthreads();

    // Layers 2 and 3
    for (int l = 0; l < 2; ++l) {
        const float* Wt = l ? g_Wt3 : g_Wt2;
#pragma unroll
        for (int nt = 0; nt < 16; ++nt)
#pragma unroll
            for (int j = 0; j < 4; ++j) acc[nt][j] = 0.f;

        for (int kt = 0; kt < 4; ++kt) {
#pragma unroll
            for (int it = 0; it < 4; ++it) {
                int i = tid + it * 256;
                int n = i >> 3, q = i & 7;
                float4 w = *(const float4*)(Wt + (size_t)n * 128 + kt * 32 + q * 4);
                *(float4*)(ws + n * WS_STRIDE + q * 4) = w;
            }
            __syncthreads();
#pragma unroll
            for (int ks = 0; ks < 4; ++ks) {
                uint32_t a[4];
                ldsm4(a, aH + (uint32_t)((kt * 32 + ks * 8) * 4));
#pragma unroll
                for (int nt2 = 0; nt2 < 8; ++nt2) {
                    uint32_t b[4];
                    ldsm4(b, bW + (uint32_t)((nt2 * 16 * WS_STRIDE + ks * 8) * 4));
                    MMA_TF32(acc[nt2 * 2],     a[0], a[1], a[2], a[3], b[0], b[1]);
                    MMA_TF32(acc[nt2 * 2 + 1], a[0], a[1], a[2], a[3], b[2], b[3]);
                }
            }
            __syncthreads();
        }

        if (l == 0) {
#pragma unroll
            for (int nt = 0; nt < 16; ++nt) {
                int col = nt * 8 + tig * 2;
                float2 v0, v1;
                v0.x = to_tf32(fmaxf(acc[nt][0] + sBias[128 + col], 0.f));
                v0.y = to_tf32(fmaxf(acc[nt][1] + sBias[128 + col + 1], 0.f));
                v1.x = to_tf32(fmaxf(acc[nt][2] + sBias[128 + col], 0.f));
                v1.y = to_tf32(fmaxf(acc[nt][3] + sBias[128 + col + 1], 0.f));
                *(float2*)(hs + r0 * HS_STRIDE + col) = v0;
                *(float2*)(hs + (r0 + 8) * HS_STRIDE + col) = v1;
            }
            __syncthreads();
        }
    }

    // Final: +b3, LayerNorm, gamma/beta, residual
    {
        float s0 = 0.f, sq0 = 0.f, s1 = 0.f, sq1 = 0.f;
#pragma unroll
        for (int nt = 0; nt < 16; ++nt) {
            int col = nt * 8 + tig * 2;
            acc[nt][0] += sBias[256 + col];
            acc[nt][1] += sBias[256 + col + 1];
            acc[nt][2] += sBias[256 + col];
            acc[nt][3] += sBias[256 + col + 1];
            s0 += acc[nt][0] + acc[nt][1];
            sq0 += acc[nt][0] * acc[nt][0] + acc[nt][1] * acc[nt][1];
            s1 += acc[nt][2] + acc[nt][3];
            sq1 += acc[nt][2] * acc[nt][2] + acc[nt][3] * acc[nt][3];
        }
#pragma unroll
        for (int o = 1; o <= 2; o <<= 1) {
            s0 += __shfl_xor_sync(0xFFFFFFFFu, s0, o);
            sq0 += __shfl_xor_sync(0xFFFFFFFFu, sq0, o);
            s1 += __shfl_xor_sync(0xFFFFFFFFu, s1, o);
            sq1 += __shfl_xor_sync(0xFFFFFFFFu, sq1, o);
        }
        float mu0 = s0 * (1.f / 128.f);
        float ri0 = rsqrtf(sq0 * (1.f / 128.f) - mu0 * mu0 + EPS);
        float mu1 = s1 * (1.f / 128.f);
        float ri1 = rsqrtf(sq1 * (1.f / 128.f) - mu1 * mu1 + EPS);

        int n0 = base + r0;
        int n1 = base + r0 + 8;
#pragma unroll
        for (int nt = 0; nt < 16; ++nt) {
            int col = nt * 8 + tig * 2;
            float g0 = sBias[384 + col], g1 = sBias[384 + col + 1];
            float be0 = sBias[512 + col], be1 = sBias[512 + col + 1];
            if (n0 < N_NODE) {
                float2 nv = *(const float2*)(nf + (size_t)n0 * FD + col);
                float2 o;
                o.x = (acc[nt][0] - mu0) * ri0 * g0 + be0 + nv.x;
                o.y = (acc[nt][1] - mu0) * ri0 * g1 + be1 + nv.y;
                *(float2*)(out + (size_t)n0 * FD + col) = o;
            }
            if (n1 < N_NODE) {
                float2 nv = *(const float2*)(nf + (size_t)n1 * FD + col);
                float2 o;
                o.x = (acc[nt][2] - mu1) * ri1 * g0 + be0 + nv.x;
                o.y = (acc[nt][3] - mu1) * ri1 * g1 + be1 + nv.y;
                *(float2*)(out + (size_t)n1 * FD + col) = o;
            }
        }
    }
}

// ---------------------------------------------------------------------------
extern "C" void kernel_launch(void* const* d_in, const int* in_sizes, int n_in,
                              void* d_out, int out_size) {
    const float* node_feature = (const float*)d_in[0];
    const int* edge_matrix    = (const int*)d_in[1];
    const float* edge_feature = (const float*)d_in[2];
    const float* W1 = (const float*)d_in[3];
    const float* b1 = (const float*)d_in[4];
    const float* W2 = (const float*)d_in[5];
    const float* b2 = (const float*)d_in[6];
    const float* W3 = (const float*)d_in[7];
    const float* b3 = (const float*)d_in[8];
    const float* gamma = (const float*)d_in[9];
    const float* beta  = (const float*)d_in[10];
    float* out = (float*)d_out;

    static void* agg_ptr = nullptr;
    static int inited = 0;
    if (!inited) {
        cudaGetSymbolAddress(&agg_ptr, g_agg);
        cudaFuncSetAttribute(mlp_mma_kernel,
                             cudaFuncAttributeMaxDynamicSharedMemorySize, SMEM_BYTES);
        inited = 1;
    }

    cudaMemsetAsync(agg_ptr, 0, (size_t)N_NODE * FD * sizeof(float));

    // 4 edges per warp, 8 warps per block
    int nwarp = (N_EDGE + 3) / 4;
    scatter_edges_kernel<<<(nwarp + 7) / 8, 256>>>(edge_matrix, edge_feature);

    prep_weights_kernel<<<(256 * 128 + 2 * 128 * 128 + 255) / 256, 256>>>(W1, W2, W3);

    int grid = (N_NODE + TM - 1) / TM;
    mlp_mma_kernel<<<grid, 256, SMEM_BYTES>>>(node_feature, b1, b2, b3,
                                              gamma, beta, out);
}